// round 8
// baseline (speedup 1.0000x reference)
#include <cuda_runtime.h>

#define NN 100000
#define NE 600000
#define NG 512
#define FD 128
#define SCAN_B 1024
#define NB_SCAN ((NN + SCAN_B - 1) / SCAN_B)   // 98

typedef unsigned long long u64;

// Scratch (allocation-free rule: __device__ globals). No float atomics anywhere.
__device__ float g_hw [NN * FD];   // h @ W
__device__ float g_agg[NN * FD];   // aggregated layer output
__device__ float g_dis[NN];        // deg^{-1/2}
__device__ int   g_deg[NN];        // in-degree (excluding self loop)
__device__ int   g_scan[NN];       // inclusive per-block scan
__device__ int   g_bsum[NB_SCAN];
__device__ int   g_boff[NB_SCAN];
__device__ int   g_rowstart[NN];   // CSR row starts (exclusive scan)
__device__ int   g_cursor[NN];     // fill cursors
__device__ int   g_csrc[NE];       // CSR: src lists grouped by dst
__device__ int   g_gstart[NG + 1]; // graph segment starts (batch is sorted)

// Packed fp32x2 FMA (FFMA2): 2 IEEE fp32 FMAs per instruction, same rt as FFMA.
__device__ __forceinline__ u64 pack2(float a) {
    u64 d; asm("mov.b64 %0, {%1, %1};" : "=l"(d) : "f"(a)); return d;
}
__device__ __forceinline__ void ffma2(u64& d, u64 a, u64 b) {
    asm("fma.rn.f32x2 %0, %1, %2, %0;" : "+l"(d) : "l"(a), "l"(b));
}

// ---------------------------------------------------------------------------
__global__ void k_zero() {
    int i = blockIdx.x * blockDim.x + threadIdx.x;
    if (i < NN) g_deg[i] = 0;
}

// in-degree count over edge dst (int atomics only). ei is int32: [src[NE], dst[NE]]
__global__ void k_count(const int* __restrict__ ei) {
    int e = blockIdx.x * blockDim.x + threadIdx.x;
    if (e < NE) atomicAdd(&g_deg[ei[NE + e]], 1);
}

// per-1024-block inclusive scan of g_deg
__global__ void __launch_bounds__(SCAN_B) k_scan1() {
    __shared__ int s[SCAN_B];
    int tid = threadIdx.x;
    int i = blockIdx.x * SCAN_B + tid;
    s[tid] = (i < NN) ? g_deg[i] : 0;
    __syncthreads();
#pragma unroll
    for (int off = 1; off < SCAN_B; off <<= 1) {
        int v = (tid >= off) ? s[tid - off] : 0;
        __syncthreads();
        s[tid] += v;
        __syncthreads();
    }
    if (i < NN) g_scan[i] = s[tid];
    if (tid == SCAN_B - 1) g_bsum[blockIdx.x] = s[tid];
}

// parallel scan of the 98 block sums (was single-threaded: 8.7us)
__global__ void __launch_bounds__(128) k_scan2() {
    __shared__ int s[128];
    int t = threadIdx.x;
    int v = (t < NB_SCAN) ? g_bsum[t] : 0;
    s[t] = v;
    __syncthreads();
#pragma unroll
    for (int off = 1; off < 128; off <<= 1) {
        int u = (t >= off) ? s[t - off] : 0;
        __syncthreads();
        s[t] += u;
        __syncthreads();
    }
    if (t < NB_SCAN) g_boff[t] = s[t] - v;   // exclusive
}

// finalize: exclusive row starts, cursors, and normalization dis = rsqrt(1+deg)
__global__ void k_scan3() {
    int i = blockIdx.x * blockDim.x + threadIdx.x;
    if (i < NN) {
        int excl = g_scan[i] + g_boff[i >> 10] - g_deg[i];
        g_rowstart[i] = excl;
        g_cursor[i]   = excl;
        g_dis[i] = rsqrtf(1.0f + (float)g_deg[i]);
    }
}

// CSR fill
__global__ void k_fill(const int* __restrict__ ei) {
    int e = blockIdx.x * blockDim.x + threadIdx.x;
    if (e < NE) {
        int s = ei[e];
        int d = ei[NE + e];
        int pos = atomicAdd(&g_cursor[d], 1);
        g_csrc[pos] = s;
    }
}

// graph segment starts from SORTED batch: gstart[g] = first n with batch[n] >= g
__global__ void k_gstart(const int* __restrict__ batch) {
    int i = blockIdx.x * blockDim.x + threadIdx.x;
    if (i <= NN) {
        int prev = (i == 0) ? -1 : batch[i - 1];
        int cur  = (i < NN) ? batch[i] : NG;
        for (int g = prev + 1; g <= cur; g++) g_gstart[g] = i;
    }
}

// ---------------------------------------------------------------------------
// GEMM: Out[NN,128] = f(A)[NN,128] @ W[128,128] via packed FFMA2.
// Block: 64 rows x 128 cols, 256 threads. Micro-tile: 4 rows x 4 col-pairs.
template <bool RELU_BIAS>
__global__ void __launch_bounds__(256) k_gemm(
    const float* __restrict__ A, const float* __restrict__ W,
    const float* __restrict__ bias, float* __restrict__ Out)
{
    __shared__ float Xs[32][68];    // [k][row]; stride 272B keeps float4 align
    __shared__ float Ws[32][128];   // [k][col]

    const int block_row = blockIdx.x * 64;
    const int tid = threadIdx.x;
    const int tr = tid >> 4;        // 0..15  row group (4 rows each)
    const int tc = tid & 15;        // 0..15  col group (8 cols = 4 pairs)

    u64 acc[4][4] = {};             // (0.0f,0.0f) packed zeros

    for (int k0 = 0; k0 < FD; k0 += 32) {
        // stage X tile (64 rows x 32 k): float4 loads, transposed scalar stores
        for (int idx = tid; idx < 512; idx += 256) {
            int r = idx >> 3, q = idx & 7;
            int row = block_row + r;
            float4 v = make_float4(0.f, 0.f, 0.f, 0.f);
            if (row < NN)
                v = *reinterpret_cast<const float4*>(&A[row * FD + k0 + q * 4]);
            if (RELU_BIAS) {
                float4 bb = *reinterpret_cast<const float4*>(&bias[k0 + q * 4]);
                v.x = fmaxf(v.x + bb.x, 0.f); v.y = fmaxf(v.y + bb.y, 0.f);
                v.z = fmaxf(v.z + bb.z, 0.f); v.w = fmaxf(v.w + bb.w, 0.f);
            }
            Xs[q * 4 + 0][r] = v.x; Xs[q * 4 + 1][r] = v.y;
            Xs[q * 4 + 2][r] = v.z; Xs[q * 4 + 3][r] = v.w;
        }
        // stage W tile (32 k x 128 cols): float4 both ways
        for (int idx = tid; idx < 1024; idx += 256) {
            int r = idx >> 5, c = (idx & 31) * 4;
            *reinterpret_cast<float4*>(&Ws[r][c]) =
                *reinterpret_cast<const float4*>(&W[(k0 + r) * FD + c]);
        }
        __syncthreads();

#pragma unroll
        for (int k = 0; k < 32; k++) {
            float4 a4 = *reinterpret_cast<const float4*>(&Xs[k][tr * 4]);
            u64 a2[4] = { pack2(a4.x), pack2(a4.y), pack2(a4.z), pack2(a4.w) };
            const u64* bp = reinterpret_cast<const u64*>(&Ws[k][tc * 8]);
            u64 b[4] = { bp[0], bp[1], bp[2], bp[3] };
#pragma unroll
            for (int i = 0; i < 4; i++)
#pragma unroll
                for (int p = 0; p < 4; p++)
                    ffma2(acc[i][p], a2[i], b[p]);
        }
        __syncthreads();
    }

#pragma unroll
    for (int i = 0; i < 4; i++) {
        int row = block_row + tr * 4 + i;
        if (row < NN) {
            *reinterpret_cast<ulonglong2*>(&Out[row * FD + tc * 8]) =
                make_ulonglong2(acc[i][0], acc[i][1]);
            *reinterpret_cast<ulonglong2*>(&Out[row * FD + tc * 8 + 4]) =
                make_ulonglong2(acc[i][2], acc[i][3]);
        }
    }
}

// ---------------------------------------------------------------------------
// CSR gather aggregation: warp per dst node, lane = one float4 of features.
// agg[d] = dis[d]^2 * hw[d] + dis[d] * sum_{s in adj(d)} dis[s] * hw[s]
__global__ void k_gather() {
    int gid = blockIdx.x * blockDim.x + threadIdx.x;
    int n = gid >> 5;
    int lane = gid & 31;
    if (n >= NN) return;

    const float4* hw4 = reinterpret_cast<const float4*>(g_hw);
    int start = g_rowstart[n];
    int cnt   = g_deg[n];

    float4 acc = make_float4(0.f, 0.f, 0.f, 0.f);
    for (int j = 0; j < cnt; j++) {
        int s = g_csrc[start + j];          // broadcast load across warp
        float w = g_dis[s];
        float4 v = hw4[s * 32 + lane];
        acc.x += w * v.x; acc.y += w * v.y;
        acc.z += w * v.z; acc.w += w * v.w;
    }
    float dd = g_dis[n];
    float w2 = dd * dd;
    float4 self = hw4[n * 32 + lane];
    float4 o = make_float4(dd * acc.x + w2 * self.x,
                           dd * acc.y + w2 * self.y,
                           dd * acc.z + w2 * self.z,
                           dd * acc.w + w2 * self.w);
    reinterpret_cast<float4*>(g_agg)[n * 32 + lane] = o;
}

// ---------------------------------------------------------------------------
// pooling over contiguous graph segments + readout, fused. Block per graph.
__global__ void __launch_bounds__(128) k_pool_final(
    const float* __restrict__ b2, const float* __restrict__ Wlin,
    const float* __restrict__ blin, float* __restrict__ out)
{
    __shared__ float sh[128];
    int g = blockIdx.x;
    int f = threadIdx.x;
    int n0 = g_gstart[g], n1 = g_gstart[g + 1];
    int cnt = n1 - n0;

    float acc = 0.0f;
#pragma unroll 4
    for (int n = n0; n < n1; n++) acc += g_agg[n * FD + f];

    float inv = (cnt > 0) ? 1.0f / (float)cnt : 0.0f;
    float pooled = acc * inv + ((cnt > 0) ? b2[f] : 0.0f);
    sh[f] = pooled * Wlin[f];
    __syncthreads();
#pragma unroll
    for (int off = 64; off > 0; off >>= 1) {
        if (f < off) sh[f] += sh[f + off];
        __syncthreads();
    }
    if (f == 0) out[g] = sh[0] + blin[0];
}

// ---------------------------------------------------------------------------
extern "C" void kernel_launch(void* const* d_in, const int* in_sizes, int n_in,
                              void* d_out, int out_size)
{
    const float* x     = (const float*)d_in[0];
    const int*   ei    = (const int*)d_in[1];     // int32
    const int*   batch = (const int*)d_in[2];     // int32
    const float* W1    = (const float*)d_in[3];
    const float* b1    = (const float*)d_in[4];
    const float* W2    = (const float*)d_in[5];
    const float* b2    = (const float*)d_in[6];
    const float* Wlin  = (const float*)d_in[7];
    const float* blin  = (const float*)d_in[8];
    float* out = (float*)d_out;

    void *p_hw, *p_agg;
    cudaGetSymbolAddress(&p_hw,  g_hw);
    cudaGetSymbolAddress(&p_agg, g_agg);
    float* hw  = (float*)p_hw;
    float* agg = (float*)p_agg;

    const int T = 256;
    const int nn_blocks   = (NN + T - 1) / T;
    const int ne_blocks   = (NE + T - 1) / T;
    const int gemm_blocks = (NN + 63) / 64;
    const int gat_blocks  = (NN * 32 + T - 1) / T;

    // CSR build + normalization + graph segments
    k_zero  <<<nn_blocks, T>>>();
    k_count <<<ne_blocks, T>>>(ei);
    k_scan1 <<<NB_SCAN, SCAN_B>>>();
    k_scan2 <<<1, 128>>>();
    k_scan3 <<<nn_blocks, T>>>();
    k_fill  <<<ne_blocks, T>>>(ei);
    k_gstart<<<(NN + 1 + T - 1) / T, T>>>(batch);

    // Layer 1: hw = x @ W1 ; agg = A_norm @ hw (bias+relu folded into gemm2 load)
    k_gemm<false><<<gemm_blocks, T>>>(x, W1, nullptr, hw);
    k_gather     <<<gat_blocks, T>>>();

    // Layer 2: hw = relu(agg + b1) @ W2 ; agg = A_norm @ hw
    k_gemm<true> <<<gemm_blocks, T>>>(agg, W2, b1, hw);
    k_gather     <<<gat_blocks, T>>>();

    // Mean-pool (contiguous segments) + readout, b2 folded with empty-graph guard
    k_pool_final <<<NG, 128>>>(b2, Wlin, blin, out);
}

// round 9
// speedup vs baseline: 1.1380x; 1.1380x over previous
#include <cuda_runtime.h>

#define NN 100000
#define NE 600000
#define NG 512
#define FD 128
#define SCAN_B 1024
#define NB_SCAN ((NN + SCAN_B - 1) / SCAN_B)   // 98

typedef unsigned long long u64;

// Scratch (allocation-free rule: __device__ globals). No float atomics anywhere.
__device__ float g_hw [NN * FD];   // h @ W
__device__ float g_agg[NN * FD];   // aggregated layer output
__device__ float g_dis[NN];        // deg^{-1/2}
__device__ int   g_deg[NN];        // in-degree (excluding self loop)
__device__ int   g_scan[NN];       // inclusive per-block scan
__device__ int   g_bsum[NB_SCAN];
__device__ int   g_boff[NB_SCAN];
__device__ int   g_rowstart[NN];   // CSR row starts (exclusive scan)
__device__ int   g_cursor[NN];     // fill cursors
__device__ int   g_csrc[NE];       // CSR: src lists grouped by dst
__device__ int   g_gstart[NG + 1]; // graph segment starts (batch is sorted)

// Packed fp32x2 FMA (FFMA2): 2 IEEE fp32 FMAs per instruction, same rt as FFMA.
__device__ __forceinline__ u64 pack2(float a) {
    u64 d; asm("mov.b64 %0, {%1, %1};" : "=l"(d) : "f"(a)); return d;
}
__device__ __forceinline__ void ffma2(u64& d, u64 a, u64 b) {
    asm("fma.rn.f32x2 %0, %1, %2, %0;" : "+l"(d) : "l"(a), "l"(b));
}

// ---------------------------------------------------------------------------
__global__ void k_zero() {
    int i = blockIdx.x * blockDim.x + threadIdx.x;
    if (i < NN) g_deg[i] = 0;
}

// in-degree count over edge dst (int atomics only). ei is int32: [src[NE], dst[NE]]
__global__ void k_count(const int* __restrict__ ei) {
    int e = blockIdx.x * blockDim.x + threadIdx.x;
    if (e < NE) atomicAdd(&g_deg[ei[NE + e]], 1);
}

// per-1024-block inclusive scan of g_deg
__global__ void __launch_bounds__(SCAN_B) k_scan1() {
    __shared__ int s[SCAN_B];
    int tid = threadIdx.x;
    int i = blockIdx.x * SCAN_B + tid;
    s[tid] = (i < NN) ? g_deg[i] : 0;
    __syncthreads();
#pragma unroll
    for (int off = 1; off < SCAN_B; off <<= 1) {
        int v = (tid >= off) ? s[tid - off] : 0;
        __syncthreads();
        s[tid] += v;
        __syncthreads();
    }
    if (i < NN) g_scan[i] = s[tid];
    if (tid == SCAN_B - 1) g_bsum[blockIdx.x] = s[tid];
}

// parallel scan of the 98 block sums
__global__ void __launch_bounds__(128) k_scan2() {
    __shared__ int s[128];
    int t = threadIdx.x;
    int v = (t < NB_SCAN) ? g_bsum[t] : 0;
    s[t] = v;
    __syncthreads();
#pragma unroll
    for (int off = 1; off < 128; off <<= 1) {
        int u = (t >= off) ? s[t - off] : 0;
        __syncthreads();
        s[t] += u;
        __syncthreads();
    }
    if (t < NB_SCAN) g_boff[t] = s[t] - v;   // exclusive
}

// finalize: exclusive row starts, cursors, and normalization dis = rsqrt(1+deg)
__global__ void k_scan3() {
    int i = blockIdx.x * blockDim.x + threadIdx.x;
    if (i < NN) {
        int excl = g_scan[i] + g_boff[i >> 10] - g_deg[i];
        g_rowstart[i] = excl;
        g_cursor[i]   = excl;
        g_dis[i] = rsqrtf(1.0f + (float)g_deg[i]);
    }
}

// CSR fill
__global__ void k_fill(const int* __restrict__ ei) {
    int e = blockIdx.x * blockDim.x + threadIdx.x;
    if (e < NE) {
        int s = ei[e];
        int d = ei[NE + e];
        int pos = atomicAdd(&g_cursor[d], 1);
        g_csrc[pos] = s;
    }
}

// graph segment starts from SORTED batch: gstart[g] = first n with batch[n] >= g
__global__ void k_gstart(const int* __restrict__ batch) {
    int i = blockIdx.x * blockDim.x + threadIdx.x;
    if (i <= NN) {
        int prev = (i == 0) ? -1 : batch[i - 1];
        int cur  = (i < NN) ? batch[i] : NG;
        for (int g = prev + 1; g <= cur; g++) g_gstart[g] = i;
    }
}

// ---------------------------------------------------------------------------
// GEMM: Out[NN,128] = f(A)[NN,128] @ W[128,128] via packed FFMA2.
// Block: 128 rows x 128 cols, 256 threads. Micro-tile: 8 rows x 4 col-pairs.
template <bool RELU_BIAS>
__global__ void __launch_bounds__(256) k_gemm(
    const float* __restrict__ A, const float* __restrict__ W,
    const float* __restrict__ bias, float* __restrict__ Out)
{
    __shared__ float Xs[32][132];   // [k][row]; 132*4=528B row stride, 16B aligned
    __shared__ float Ws[32][128];   // [k][col]

    const int block_row = blockIdx.x * 128;
    const int tid = threadIdx.x;
    const int tr = tid >> 4;        // 0..15  row group (8 rows each)
    const int tc = tid & 15;        // 0..15  col group (8 cols = 4 pairs)

    u64 acc[8][4] = {};             // (0.0f,0.0f) packed zeros

    for (int k0 = 0; k0 < FD; k0 += 32) {
        // stage X tile (128 rows x 32 k): float4 loads, transposed scalar stores
        for (int idx = tid; idx < 1024; idx += 256) {
            int r = idx >> 3, q = idx & 7;
            int row = block_row + r;
            float4 v = make_float4(0.f, 0.f, 0.f, 0.f);
            if (row < NN)
                v = *reinterpret_cast<const float4*>(&A[row * FD + k0 + q * 4]);
            if (RELU_BIAS) {
                float4 bb = *reinterpret_cast<const float4*>(&bias[k0 + q * 4]);
                v.x = fmaxf(v.x + bb.x, 0.f); v.y = fmaxf(v.y + bb.y, 0.f);
                v.z = fmaxf(v.z + bb.z, 0.f); v.w = fmaxf(v.w + bb.w, 0.f);
            }
            Xs[q * 4 + 0][r] = v.x; Xs[q * 4 + 1][r] = v.y;
            Xs[q * 4 + 2][r] = v.z; Xs[q * 4 + 3][r] = v.w;
        }
        // stage W tile (32 k x 128 cols): float4 both ways
        for (int idx = tid; idx < 1024; idx += 256) {
            int r = idx >> 5, c = (idx & 31) * 4;
            *reinterpret_cast<float4*>(&Ws[r][c]) =
                *reinterpret_cast<const float4*>(&W[(k0 + r) * FD + c]);
        }
        __syncthreads();

#pragma unroll
        for (int k = 0; k < 32; k++) {
            float4 a0 = *reinterpret_cast<const float4*>(&Xs[k][tr * 8]);
            float4 a1 = *reinterpret_cast<const float4*>(&Xs[k][tr * 8 + 4]);
            u64 a2[8] = { pack2(a0.x), pack2(a0.y), pack2(a0.z), pack2(a0.w),
                          pack2(a1.x), pack2(a1.y), pack2(a1.z), pack2(a1.w) };
            const u64* bp = reinterpret_cast<const u64*>(&Ws[k][tc * 8]);
            u64 b[4] = { bp[0], bp[1], bp[2], bp[3] };
#pragma unroll
            for (int i = 0; i < 8; i++)
#pragma unroll
                for (int p = 0; p < 4; p++)
                    ffma2(acc[i][p], a2[i], b[p]);
        }
        __syncthreads();
    }

#pragma unroll
    for (int i = 0; i < 8; i++) {
        int row = block_row + tr * 8 + i;
        if (row < NN) {
            *reinterpret_cast<ulonglong2*>(&Out[row * FD + tc * 8]) =
                make_ulonglong2(acc[i][0], acc[i][1]);
            *reinterpret_cast<ulonglong2*>(&Out[row * FD + tc * 8 + 4]) =
                make_ulonglong2(acc[i][2], acc[i][3]);
        }
    }
}

// ---------------------------------------------------------------------------
// CSR gather aggregation: warp per dst node, lane = one float4 of features.
// agg[d] = dis[d]^2 * hw[d] + dis[d] * sum_{s in adj(d)} dis[s] * hw[s]
// Chunked x4: batch index/weight loads before row loads for MLP.
__global__ void k_gather() {
    int gid = blockIdx.x * blockDim.x + threadIdx.x;
    int n = gid >> 5;
    int lane = gid & 31;
    if (n >= NN) return;

    const float4* hw4 = reinterpret_cast<const float4*>(g_hw);
    int start = g_rowstart[n];
    int cnt   = g_deg[n];

    float4 acc = make_float4(0.f, 0.f, 0.f, 0.f);
    int j = 0;
    for (; j + 4 <= cnt; j += 4) {
        int s0 = g_csrc[start + j + 0];
        int s1 = g_csrc[start + j + 1];
        int s2 = g_csrc[start + j + 2];
        int s3 = g_csrc[start + j + 3];
        float w0 = g_dis[s0], w1 = g_dis[s1], w2 = g_dis[s2], w3 = g_dis[s3];
        float4 v0 = hw4[s0 * 32 + lane];
        float4 v1 = hw4[s1 * 32 + lane];
        float4 v2 = hw4[s2 * 32 + lane];
        float4 v3 = hw4[s3 * 32 + lane];
        acc.x += w0 * v0.x + w1 * v1.x + w2 * v2.x + w3 * v3.x;
        acc.y += w0 * v0.y + w1 * v1.y + w2 * v2.y + w3 * v3.y;
        acc.z += w0 * v0.z + w1 * v1.z + w2 * v2.z + w3 * v3.z;
        acc.w += w0 * v0.w + w1 * v1.w + w2 * v2.w + w3 * v3.w;
    }
    for (; j < cnt; j++) {
        int s = g_csrc[start + j];
        float w = g_dis[s];
        float4 v = hw4[s * 32 + lane];
        acc.x += w * v.x; acc.y += w * v.y;
        acc.z += w * v.z; acc.w += w * v.w;
    }
    float dd = g_dis[n];
    float w2s = dd * dd;
    float4 self = hw4[n * 32 + lane];
    float4 o = make_float4(dd * acc.x + w2s * self.x,
                           dd * acc.y + w2s * self.y,
                           dd * acc.z + w2s * self.z,
                           dd * acc.w + w2s * self.w);
    reinterpret_cast<float4*>(g_agg)[n * 32 + lane] = o;
}

// ---------------------------------------------------------------------------
// pooling over contiguous graph segments + readout, fused. Block per graph.
__global__ void __launch_bounds__(128) k_pool_final(
    const float* __restrict__ b2, const float* __restrict__ Wlin,
    const float* __restrict__ blin, float* __restrict__ out)
{
    __shared__ float sh[128];
    int g = blockIdx.x;
    int f = threadIdx.x;
    int n0 = g_gstart[g], n1 = g_gstart[g + 1];
    int cnt = n1 - n0;

    float acc = 0.0f;
#pragma unroll 4
    for (int n = n0; n < n1; n++) acc += g_agg[n * FD + f];

    float inv = (cnt > 0) ? 1.0f / (float)cnt : 0.0f;
    float pooled = acc * inv + ((cnt > 0) ? b2[f] : 0.0f);
    sh[f] = pooled * Wlin[f];
    __syncthreads();
#pragma unroll
    for (int off = 64; off > 0; off >>= 1) {
        if (f < off) sh[f] += sh[f + off];
        __syncthreads();
    }
    if (f == 0) out[g] = sh[0] + blin[0];
}

// ---------------------------------------------------------------------------
extern "C" void kernel_launch(void* const* d_in, const int* in_sizes, int n_in,
                              void* d_out, int out_size)
{
    const float* x     = (const float*)d_in[0];
    const int*   ei    = (const int*)d_in[1];     // int32
    const int*   batch = (const int*)d_in[2];     // int32
    const float* W1    = (const float*)d_in[3];
    const float* b1    = (const float*)d_in[4];
    const float* W2    = (const float*)d_in[5];
    const float* b2    = (const float*)d_in[6];
    const float* Wlin  = (const float*)d_in[7];
    const float* blin  = (const float*)d_in[8];
    float* out = (float*)d_out;

    void *p_hw, *p_agg;
    cudaGetSymbolAddress(&p_hw,  g_hw);
    cudaGetSymbolAddress(&p_agg, g_agg);
    float* hw  = (float*)p_hw;
    float* agg = (float*)p_agg;

    const int T = 256;
    const int nn_blocks   = (NN + T - 1) / T;
    const int ne_blocks   = (NE + T - 1) / T;
    const int gemm_blocks = (NN + 127) / 128;
    const int gat_blocks  = (NN * 32 + T - 1) / T;

    // Launch order puts gemm1 at my launch index 3 (0-based) so the ncu
    // capture window (-s 5 -c 1, with 2 harness pre-launches) lands on it.
    k_zero       <<<nn_blocks, T>>>();
    k_count      <<<ne_blocks, T>>>(ei);
    k_scan1      <<<NB_SCAN, SCAN_B>>>();
    k_gemm<false><<<gemm_blocks, T>>>(x, W1, nullptr, hw);   // layer-1 GEMM (no CSR dep)
    k_scan2      <<<1, 128>>>();
    k_scan3      <<<nn_blocks, T>>>();
    k_fill       <<<ne_blocks, T>>>(ei);
    k_gstart     <<<(NN + 1 + T - 1) / T, T>>>(batch);

    // Layer 1 aggregation, then layer 2
    k_gather     <<<gat_blocks, T>>>();
    k_gemm<true> <<<gemm_blocks, T>>>(agg, W2, b1, hw);
    k_gather     <<<gat_blocks, T>>>();

    // Mean-pool (contiguous segments) + readout, b2 folded with empty-graph guard
    k_pool_final <<<NG, 128>>>(b2, Wlin, blin, out);
}